// round 11
// baseline (speedup 1.0000x reference)
#include <cuda_runtime.h>
#include <cuda_fp16.h>
#include <math.h>
#include <stdint.h>

#define SEQ    16384
#define HIDDEN 4096
#define NHEADS 32
#define RLAT   64

#define BM 256
#define BN 128
#define BK 32
#define NSTAGE 4
#define APITCH 40     // fp16 elems per A smem row (80B: conflict-free ldmatrix)
#define BPITCH 136    // fp16 elems per B smem row
#define KTILES (HIDDEN / BK)   // 128

#define A_ST (BM * APITCH)     // halves per A stage (10240)
#define B_ST (BK * BPITCH)     // halves per B stage (4352)
#define GEMM_SMEM_BYTES ((NSTAGE * (A_ST + B_ST)) * 2)   // 116,736 B

// ---------------- scratch (static device globals; no allocation) -----------
__device__ __half g_qh[(size_t)SEQ * HIDDEN];   // query fp16
__device__ __half g_ah[(size_t)SEQ * HIDDEN];   // attention out fp16
__device__ __half g_oh[(size_t)SEQ * HIDDEN];   // 'out' fp16
__device__ __half g_hh[(size_t)SEQ * HIDDEN];   // gelu hidden fp16
__device__ float  g_of[(size_t)SEQ * HIDDEN];   // 'out' fp32 (residual)
__device__ __half g_wqh[(size_t)HIDDEN * HIDDEN];
__device__ __half g_woh[(size_t)HIDDEN * HIDDEN];
__device__ __half g_w1h[(size_t)HIDDEN * HIDDEN];
__device__ __half g_w2h[(size_t)HIDDEN * HIDDEN];

// ---------------- small helpers -------------------------------------------
__device__ __forceinline__ uint32_t smem_u32(const void* p) {
    return (uint32_t)__cvta_generic_to_shared(p);
}
__device__ __forceinline__ void cp16(uint32_t s, const void* g) {
    asm volatile("cp.async.cg.shared.global [%0], [%1], 16;\n" :: "r"(s), "l"(g));
}
#define CP_COMMIT() asm volatile("cp.async.commit_group;\n")
#define CP_WAIT2()  asm volatile("cp.async.wait_group 2;\n")

__device__ __forceinline__ void ldsm4(uint32_t& r0, uint32_t& r1, uint32_t& r2,
                                      uint32_t& r3, uint32_t a) {
    asm volatile("ldmatrix.sync.aligned.m8n8.x4.shared.b16 {%0,%1,%2,%3}, [%4];\n"
                 : "=r"(r0), "=r"(r1), "=r"(r2), "=r"(r3) : "r"(a));
}
__device__ __forceinline__ void ldsm4t(uint32_t& r0, uint32_t& r1, uint32_t& r2,
                                       uint32_t& r3, uint32_t a) {
    asm volatile("ldmatrix.sync.aligned.m8n8.x4.trans.shared.b16 {%0,%1,%2,%3}, [%4];\n"
                 : "=r"(r0), "=r"(r1), "=r"(r2), "=r"(r3) : "r"(a));
}
__device__ __forceinline__ void mma16816(float* d, const uint32_t* a, const uint32_t* b) {
    asm volatile(
        "mma.sync.aligned.m16n8k16.row.col.f32.f16.f16.f32 "
        "{%0,%1,%2,%3}, {%4,%5,%6,%7}, {%8,%9}, {%0,%1,%2,%3};\n"
        : "+f"(d[0]), "+f"(d[1]), "+f"(d[2]), "+f"(d[3])
        : "r"(a[0]), "r"(a[1]), "r"(a[2]), "r"(a[3]), "r"(b[0]), "r"(b[1]));
}
__device__ __forceinline__ float gelu_exact(float x) {
    return 0.5f * x * (1.0f + erff(x * 0.70710678118654752f));
}

// ---------------- fp32 -> fp16 conversion ----------------------------------
__global__ __launch_bounds__(256)
void cvt_kernel(const float* __restrict__ in, __half* __restrict__ out, int n4) {
    int i = blockIdx.x * blockDim.x + threadIdx.x;
    int stride = gridDim.x * blockDim.x;
    for (; i < n4; i += stride) {
        float4 v = ((const float4*)in)[i];
        ((__half2*)out)[2 * i + 0] = __floats2half2_rn(v.x, v.y);
        ((__half2*)out)[2 * i + 1] = __floats2half2_rn(v.z, v.w);
    }
}

// ---------------- shared mainloop: 256x128 CTA tile, 64x64 warp tile --------
// acc[4][8][4]: mi in 0..3 (rows wm*64+mi*16), nj in 0..7 (cols wn*64+nj*8)
struct GemmCore {
    __device__ __forceinline__ static void load_tile(
        __half* Asm, __half* Bsm, int u,
        const __half* Ap, const __half* Bp, int tid)
    {
        __half* A0 = Asm + (u & (NSTAGE - 1)) * A_ST;
        __half* B0 = Bsm + (u & (NSTAGE - 1)) * B_ST;
        const int kt = u * BK;
#pragma unroll
        for (int i = 0; i < 4; i++) {            // A: 1024 chunks / 256 thr
            int chunk = tid + (i << 8);
            int r = chunk >> 2, c = chunk & 3;
            cp16(smem_u32(&A0[r * APITCH + c * 8]),
                 Ap + (size_t)r * HIDDEN + kt + c * 8);
        }
#pragma unroll
        for (int i = 0; i < 2; i++) {            // B: 512 chunks / 256 thr
            int chunk = tid + (i << 8);
            int kk = chunk >> 4, bc = chunk & 15;
            cp16(smem_u32(&B0[kk * BPITCH + bc * 8]),
                 Bp + (size_t)(kt + kk) * HIDDEN + bc * 8);
        }
    }

    __device__ __forceinline__ static void run(
        float acc[4][8][4], __half* Asm, __half* Bsm,
        const __half* Ap, const __half* Bp,
        int tid, int lane, int wm, int wn)
    {
        // prologue: tiles 0..NSTAGE-2
#pragma unroll
        for (int u = 0; u < NSTAGE - 1; u++) {
            load_tile(Asm, Bsm, u, Ap, Bp, tid);
            CP_COMMIT();
        }

        for (int t = 0; t < KTILES; t++) {
            CP_WAIT2();
            __syncthreads();

            int un = t + NSTAGE - 1;
            if (un < KTILES)
                load_tile(Asm, Bsm, un, Ap, Bp, tid);
            CP_COMMIT();   // empty group in tail keeps wait depth uniform

            __half* Ac = Asm + (t & (NSTAGE - 1)) * A_ST;
            __half* Bc = Bsm + (t & (NSTAGE - 1)) * B_ST;
#pragma unroll
            for (int ks = 0; ks < 2; ks++) {
                const int k0 = ks * 16;
                uint32_t a[4][4];
#pragma unroll
                for (int mi = 0; mi < 4; mi++) {
                    int m = wm * 64 + mi * 16 + (lane & 15);
                    ldsm4(a[mi][0], a[mi][1], a[mi][2], a[mi][3],
                          smem_u32(&Ac[m * APITCH + k0 + (lane >> 4) * 8]));
                }
                uint32_t b[4][4];
#pragma unroll
                for (int nj = 0; nj < 4; nj++) {
                    int kk = k0 + (lane & 15);
                    int n = wn * 64 + nj * 16 + (lane >> 4) * 8;
                    ldsm4t(b[nj][0], b[nj][1], b[nj][2], b[nj][3],
                           smem_u32(&Bc[kk * BPITCH + n]));
                }
#pragma unroll
                for (int mi = 0; mi < 4; mi++)
#pragma unroll
                    for (int nj = 0; nj < 4; nj++) {
                        mma16816(acc[mi][2 * nj + 0], a[mi], &b[nj][0]);
                        mma16816(acc[mi][2 * nj + 1], a[mi], &b[nj][2]);
                    }
            }
        }
    }
};

// ---------------- generic GEMM: C = epi(A @ B) -----------------------------
// OUTMODE: 0 = fp16 only, 1 = fp32 only, 2 = both
template <int OUTMODE, bool HASBIAS, bool GELU, bool RESID>
__global__ __launch_bounds__(256, 1)
void hgemm_kernel(const __half* __restrict__ A, const __half* __restrict__ B,
                  const float* __restrict__ bias, const float* __restrict__ resid,
                  float* __restrict__ Cf, __half* __restrict__ Ch)
{
    extern __shared__ __align__(16) char dsm[];
    __half* Asm = (__half*)dsm;
    __half* Bsm = Asm + NSTAGE * A_ST;

    const int nyb = HIDDEN / BN;  // 32
    const int xb = blockIdx.x / nyb;
    const int yb = blockIdx.x % nyb;
    const int rowBase = xb * BM;
    const int colBase = yb * BN;

    const int tid = threadIdx.x;
    const int lane = tid & 31;
    const int warp = tid >> 5;
    const int wm = warp >> 1, wn = warp & 1;

    float acc[4][8][4];
#pragma unroll
    for (int i = 0; i < 4; i++)
#pragma unroll
        for (int j = 0; j < 8; j++)
#pragma unroll
            for (int k = 0; k < 4; k++) acc[i][j][k] = 0.0f;

    GemmCore::run(acc, Asm, Bsm,
                  A + (size_t)rowBase * HIDDEN, B + colBase,
                  tid, lane, wm, wn);

    // epilogue
#pragma unroll
    for (int mi = 0; mi < 4; mi++) {
        int r0 = rowBase + wm * 64 + mi * 16 + (lane >> 2);
#pragma unroll
        for (int nj = 0; nj < 8; nj++) {
            int col = colBase + wn * 64 + nj * 8 + (lane & 3) * 2;
            float v0 = acc[mi][nj][0], v1 = acc[mi][nj][1];
            float v2 = acc[mi][nj][2], v3 = acc[mi][nj][3];
            if (HASBIAS) {
                float2 bb = *(const float2*)&bias[col];
                v0 += bb.x; v1 += bb.y; v2 += bb.x; v3 += bb.y;
            }
            if (GELU) {
                v0 = gelu_exact(v0); v1 = gelu_exact(v1);
                v2 = gelu_exact(v2); v3 = gelu_exact(v3);
            }
            if (RESID) {
                float2 ra = *(const float2*)&resid[(size_t)r0 * HIDDEN + col];
                float2 rb = *(const float2*)&resid[(size_t)(r0 + 8) * HIDDEN + col];
                v0 += ra.x; v1 += ra.y; v2 += rb.x; v3 += rb.y;
            }
            if (OUTMODE >= 1) {
                *(float2*)&Cf[(size_t)r0 * HIDDEN + col] = make_float2(v0, v1);
                *(float2*)&Cf[(size_t)(r0 + 8) * HIDDEN + col] = make_float2(v2, v3);
            }
            if (OUTMODE == 0 || OUTMODE == 2) {
                *(__half2*)&Ch[(size_t)r0 * HIDDEN + col] = __floats2half2_rn(v0, v1);
                *(__half2*)&Ch[(size_t)(r0 + 8) * HIDDEN + col] = __floats2half2_rn(v2, v3);
            }
        }
    }
}

// ---------------- fused: xq = (q @ wq)*scale -> latent attention -----------
// 256 rows per CTA; attention epilogue processes two 128-row halves.
#define XQ_PITCH 132
#define ATTN_BODY_BYTES ((128 * XQ_PITCH + 64 * XQ_PITCH + 8 * 64) * 4)
#define ATTN_SMEM_BYTES (ATTN_BODY_BYTES > GEMM_SMEM_BYTES ? ATTN_BODY_BYTES : GEMM_SMEM_BYTES)

__global__ __launch_bounds__(256, 1)
void fused_attn_kernel(const __half* __restrict__ A,   // query fp16 [SEQ,HIDDEN]
                       const __half* __restrict__ B,   // wq fp16 [HIDDEN,HIDDEN]
                       const float* __restrict__ kv,   // kv_latent fp32 [RLAT,HIDDEN]
                       __half* __restrict__ C)         // attn out fp16
{
    extern __shared__ __align__(16) char smem_raw[];
    __half* Asm = (__half*)smem_raw;
    __half* Bsm = Asm + NSTAGE * A_ST;

    const int xb = blockIdx.x / NHEADS;
    const int h  = blockIdx.x % NHEADS;
    const int rowBase = xb * BM;
    const int colBase = h * 128;   // DH = 128 = BN

    const int tid = threadIdx.x;
    const int lane = tid & 31;
    const int warp = tid >> 5;
    const int wm = warp >> 1, wn = warp & 1;

    float acc[4][8][4];
#pragma unroll
    for (int i = 0; i < 4; i++)
#pragma unroll
        for (int j = 0; j < 8; j++)
#pragma unroll
            for (int k = 0; k < 4; k++) acc[i][j][k] = 0.0f;

    GemmCore::run(acc, Asm, Bsm,
                  A + (size_t)rowBase * HIDDEN, B + colBase,
                  tid, lane, wm, wn);

    __syncthreads();   // done with GEMM smem; repurpose for attention

    float* xq  = (float*)smem_raw;              // [128][XQ_PITCH] (per half)
    float* kvs = xq + 128 * XQ_PITCH;           // [64][XQ_PITCH]
    float* ps  = kvs + 64 * XQ_PITCH;           // [8][64]

    // load kv head slice once (region disjoint from xq)
    for (int idx = tid; idx < RLAT * 32; idx += 256) {
        int r = idx >> 5, d4 = idx & 31;
        float4 v = *(const float4*)(kv + (size_t)r * HIDDEN + colBase + (d4 << 2));
        *(float4*)&kvs[r * XQ_PITCH + (d4 << 2)] = v;
    }

    const float scale = 0.125f;  // R^-0.5
    float* pw = ps + warp * 64;

    for (int half = 0; half < 2; half++) {
        // warps whose rows fall in this half write their xq slice
        if ((wm >> 1) == half) {
#pragma unroll
            for (int mi = 0; mi < 4; mi++) {
                int r0 = (wm & 1) * 64 + mi * 16 + (lane >> 2);  // local row 0..127
#pragma unroll
                for (int nj = 0; nj < 8; nj++) {
                    int c = wn * 64 + nj * 8 + (lane & 3) * 2;
                    xq[r0 * XQ_PITCH + c]           = acc[mi][nj][0] * scale;
                    xq[r0 * XQ_PITCH + c + 1]       = acc[mi][nj][1] * scale;
                    xq[(r0 + 8) * XQ_PITCH + c]     = acc[mi][nj][2] * scale;
                    xq[(r0 + 8) * XQ_PITCH + c + 1] = acc[mi][nj][3] * scale;
                }
            }
        }
        __syncthreads();

        for (int rr = 0; rr < 16; rr++) {
            int lrow = (warp << 4) + rr;             // 0..127
            const float* xrow = xq + lrow * XQ_PITCH;
            const float* k0 = kvs + lane * XQ_PITCH;
            const float* k1 = kvs + (lane + 32) * XQ_PITCH;
            float s0 = 0.0f, s1 = 0.0f;
#pragma unroll 8
            for (int d4 = 0; d4 < 32; d4++) {
                float4 xv = *(const float4*)&xrow[d4 << 2];
                float4 av = *(const float4*)&k0[d4 << 2];
                float4 bv = *(const float4*)&k1[d4 << 2];
                s0 += xv.x * av.x + xv.y * av.y + xv.z * av.z + xv.w * av.w;
                s1 += xv.x * bv.x + xv.y * bv.y + xv.z * bv.z + xv.w * bv.w;
            }
            float m = fmaxf(s0, s1);
#pragma unroll
            for (int off = 16; off > 0; off >>= 1)
                m = fmaxf(m, __shfl_xor_sync(0xffffffffu, m, off));
            float e0 = __expf(s0 - m), e1 = __expf(s1 - m);
            float sum = e0 + e1;
#pragma unroll
            for (int off = 16; off > 0; off >>= 1)
                sum += __shfl_xor_sync(0xffffffffu, sum, off);
            float inv = 1.0f / sum;
            __syncwarp();
            pw[lane] = e0 * inv;
            pw[lane + 32] = e1 * inv;
            __syncwarp();

            float4 o = make_float4(0.f, 0.f, 0.f, 0.f);
#pragma unroll 16
            for (int r = 0; r < 64; r++) {
                float p = pw[r];
                float4 kvv = *(const float4*)&kvs[r * XQ_PITCH + (lane << 2)];
                o.x = fmaf(p, kvv.x, o.x);
                o.y = fmaf(p, kvv.y, o.y);
                o.z = fmaf(p, kvv.z, o.z);
                o.w = fmaf(p, kvv.w, o.w);
            }
            int grow = rowBase + half * 128 + lrow;
            __half* cp = C + (size_t)grow * HIDDEN + colBase + (lane << 2);
            ((__half2*)cp)[0] = __floats2half2_rn(o.x, o.y);
            ((__half2*)cp)[1] = __floats2half2_rn(o.z, o.w);
        }
        __syncthreads();   // xq region reused by next half
    }
}

// ---------------- host launcher --------------------------------------------
extern "C" void kernel_launch(void* const* d_in, const int* in_sizes, int n_in,
                              void* d_out, int out_size)
{
    const float* query = (const float*)d_in[0];
    const float* kvlat = (const float*)d_in[1];
    const float* wq    = (const float*)d_in[2];
    const float* wo    = (const float*)d_in[3];
    const float* w1    = (const float*)d_in[4];
    const float* b1    = (const float*)d_in[5];
    const float* w2    = (const float*)d_in[6];
    const float* b2    = (const float*)d_in[7];
    float* y = (float*)d_out;

    __half *qh, *ah, *oh, *hh, *wqh, *woh, *w1h, *w2h;
    float* of;
    cudaGetSymbolAddress((void**)&qh, g_qh);
    cudaGetSymbolAddress((void**)&ah, g_ah);
    cudaGetSymbolAddress((void**)&oh, g_oh);
    cudaGetSymbolAddress((void**)&hh, g_hh);
    cudaGetSymbolAddress((void**)&of, g_of);
    cudaGetSymbolAddress((void**)&wqh, g_wqh);
    cudaGetSymbolAddress((void**)&woh, g_woh);
    cudaGetSymbolAddress((void**)&w1h, g_w1h);
    cudaGetSymbolAddress((void**)&w2h, g_w2h);

    cudaFuncSetAttribute(fused_attn_kernel,
                         cudaFuncAttributeMaxDynamicSharedMemorySize,
                         ATTN_SMEM_BYTES);
    cudaFuncSetAttribute(hgemm_kernel<2, false, false, false>,
                         cudaFuncAttributeMaxDynamicSharedMemorySize,
                         GEMM_SMEM_BYTES);
    cudaFuncSetAttribute(hgemm_kernel<0, true, true, false>,
                         cudaFuncAttributeMaxDynamicSharedMemorySize,
                         GEMM_SMEM_BYTES);
    cudaFuncSetAttribute(hgemm_kernel<1, true, false, true>,
                         cudaFuncAttributeMaxDynamicSharedMemorySize,
                         GEMM_SMEM_BYTES);

    const int wn4 = (HIDDEN * HIDDEN) / 4;
    const int qn4 = (SEQ * HIDDEN) / 4;
    cvt_kernel<<<4096, 256>>>(query, qh, qn4);
    cvt_kernel<<<4096, 256>>>(wq, wqh, wn4);
    cvt_kernel<<<4096, 256>>>(wo, woh, wn4);
    cvt_kernel<<<4096, 256>>>(w1, w1h, wn4);
    cvt_kernel<<<4096, 256>>>(w2, w2h, wn4);

    const int grid = (SEQ / BM) * (HIDDEN / BN);  // 64 * 32 = 2048
    dim3 blk(256);

    // K1: ah = attention(q @ wq)
    fused_attn_kernel<<<grid, blk, ATTN_SMEM_BYTES>>>(qh, wqh, kvlat, ah);
    // K2: out = ah @ wo  -> fp32 (residual) + fp16 (next GEMM input)
    hgemm_kernel<2, false, false, false><<<grid, blk, GEMM_SMEM_BYTES>>>(
        ah, woh, nullptr, nullptr, of, oh);
    // K3: hh = gelu(out @ w1 + b1) -> fp16
    hgemm_kernel<0, true, true, false><<<grid, blk, GEMM_SMEM_BYTES>>>(
        oh, w1h, b1, nullptr, nullptr, hh);
    // K4: y = hh @ w2 + b2 + out  -> fp32
    hgemm_kernel<1, true, false, true><<<grid, blk, GEMM_SMEM_BYTES>>>(
        hh, w2h, b2, of, y, nullptr);
}

// round 14
// speedup vs baseline: 1.7227x; 1.7227x over previous
#include <cuda_runtime.h>
#include <cuda_fp16.h>
#include <math.h>
#include <stdint.h>

#define SEQ    16384
#define HIDDEN 4096
#define NHEADS 32
#define RLAT   64

#define BK 32
#define NSTAGE 4
#define APITCH 40      // fp16 elems per A smem row (80B: conflict-free ldmatrix)
#define KTILES (HIDDEN / BK)   // 128
#define A_ST (128 * APITCH)    // halves per A stage (5120), BM=128 everywhere

// GEMM kernels: BN=256, 512 threads
#define BPITCH_G 264
#define B_ST_G (BK * BPITCH_G)          // 8448 halves
#define GEMM_SMEM_BYTES ((NSTAGE * (A_ST + B_ST_G)) * 2)   // 108,544 B

// Attention kernel: BN=128, 256 threads (measured-good R8 config)
#define BPITCH_A 136
#define B_ST_A (BK * BPITCH_A)          // 4352 halves
#define ATTN_GEMM_SMEM ((NSTAGE * (A_ST + B_ST_A)) * 2)    // 75,776 B

// ---------------- scratch (static device globals; no allocation) -----------
__device__ __half g_qh[(size_t)SEQ * HIDDEN];   // query fp16
__device__ __half g_ah[(size_t)SEQ * HIDDEN];   // attention out fp16
__device__ __half g_oh[(size_t)SEQ * HIDDEN];   // 'out' fp16
__device__ __half g_hh[(size_t)SEQ * HIDDEN];   // gelu hidden fp16
__device__ float  g_of[(size_t)SEQ * HIDDEN];   // 'out' fp32 (residual)
__device__ __half g_wqh[(size_t)HIDDEN * HIDDEN];
__device__ __half g_woh[(size_t)HIDDEN * HIDDEN];
__device__ __half g_w1h[(size_t)HIDDEN * HIDDEN];
__device__ __half g_w2h[(size_t)HIDDEN * HIDDEN];

// ---------------- small helpers -------------------------------------------
__device__ __forceinline__ uint32_t smem_u32(const void* p) {
    return (uint32_t)__cvta_generic_to_shared(p);
}
__device__ __forceinline__ void cp16(uint32_t s, const void* g) {
    asm volatile("cp.async.cg.shared.global [%0], [%1], 16;\n" :: "r"(s), "l"(g));
}
#define CP_COMMIT() asm volatile("cp.async.commit_group;\n")
#define CP_WAIT2()  asm volatile("cp.async.wait_group 2;\n")

__device__ __forceinline__ void ldsm4(uint32_t& r0, uint32_t& r1, uint32_t& r2,
                                      uint32_t& r3, uint32_t a) {
    asm volatile("ldmatrix.sync.aligned.m8n8.x4.shared.b16 {%0,%1,%2,%3}, [%4];\n"
                 : "=r"(r0), "=r"(r1), "=r"(r2), "=r"(r3) : "r"(a));
}
__device__ __forceinline__ void ldsm4t(uint32_t& r0, uint32_t& r1, uint32_t& r2,
                                       uint32_t& r3, uint32_t a) {
    asm volatile("ldmatrix.sync.aligned.m8n8.x4.trans.shared.b16 {%0,%1,%2,%3}, [%4];\n"
                 : "=r"(r0), "=r"(r1), "=r"(r2), "=r"(r3) : "r"(a));
}
__device__ __forceinline__ void mma16816(float* d, const uint32_t* a, const uint32_t* b) {
    asm volatile(
        "mma.sync.aligned.m16n8k16.row.col.f32.f16.f16.f32 "
        "{%0,%1,%2,%3}, {%4,%5,%6,%7}, {%8,%9}, {%0,%1,%2,%3};\n"
        : "+f"(d[0]), "+f"(d[1]), "+f"(d[2]), "+f"(d[3])
        : "r"(a[0]), "r"(a[1]), "r"(a[2]), "r"(a[3]), "r"(b[0]), "r"(b[1]));
}
__device__ __forceinline__ float gelu_exact(float x) {
    return 0.5f * x * (1.0f + erff(x * 0.70710678118654752f));
}

// ---------------- fp32 -> fp16 conversion ----------------------------------
__global__ __launch_bounds__(256)
void cvt_kernel(const float* __restrict__ in, __half* __restrict__ out, int n4) {
    int i = blockIdx.x * blockDim.x + threadIdx.x;
    int stride = gridDim.x * blockDim.x;
    for (; i < n4; i += stride) {
        float4 v = ((const float4*)in)[i];
        ((__half2*)out)[2 * i + 0] = __floats2half2_rn(v.x, v.y);
        ((__half2*)out)[2 * i + 1] = __floats2half2_rn(v.z, v.w);
    }
}

// ---------------- shared mainloop: BM=128, warp tile 32x64 ------------------
// Template on thread count / BN. acc[2][8][4] per thread (identical to the
// measured-good R8 core). NWN = BN/64 warps across N; wm = warp / NWN.
template <int THREADS, int BN_, int BPITCH_>
struct GemmCore {
    static constexpr int B_ST_ = BK * BPITCH_;
    static constexpr int NBC = BN_ / 8;           // B chunks per k-row

    __device__ __forceinline__ static void load_tile(
        __half* Asm, __half* Bsm, int u,
        const __half* Ap, const __half* Bp, int tid)
    {
        __half* A0 = Asm + (u & (NSTAGE - 1)) * A_ST;
        __half* B0 = Bsm + (u & (NSTAGE - 1)) * B_ST_;
        const int kt = u * BK;
#pragma unroll
        for (int i = 0; i < 512 / THREADS; i++) {     // A: 512 16B chunks
            int chunk = tid + i * THREADS;
            int r = chunk >> 2, c = chunk & 3;
            cp16(smem_u32(&A0[r * APITCH + c * 8]),
                 Ap + (size_t)r * HIDDEN + kt + c * 8);
        }
#pragma unroll
        for (int i = 0; i < (BK * NBC) / THREADS; i++) {  // B chunks
            int chunk = tid + i * THREADS;
            int kk = chunk / NBC, bc = chunk % NBC;
            cp16(smem_u32(&B0[kk * BPITCH_ + bc * 8]),
                 Bp + (size_t)(kt + kk) * HIDDEN + bc * 8);
        }
    }

    __device__ __forceinline__ static void run(
        float acc[2][8][4], __half* Asm, __half* Bsm,
        const __half* Ap, const __half* Bp,
        int tid, int lane, int wm, int wn)
    {
#pragma unroll
        for (int u = 0; u < NSTAGE - 1; u++) {
            load_tile(Asm, Bsm, u, Ap, Bp, tid);
            CP_COMMIT();
        }

        for (int t = 0; t < KTILES; t++) {
            CP_WAIT2();
            __syncthreads();

            int un = t + NSTAGE - 1;
            if (un < KTILES)
                load_tile(Asm, Bsm, un, Ap, Bp, tid);
            CP_COMMIT();   // empty group in tail keeps wait depth uniform

            __half* Ac = Asm + (t & (NSTAGE - 1)) * A_ST;
            __half* Bc = Bsm + (t & (NSTAGE - 1)) * B_ST_;
#pragma unroll
            for (int ks = 0; ks < 2; ks++) {
                const int k0 = ks * 16;
                uint32_t a[2][4];
#pragma unroll
                for (int mi = 0; mi < 2; mi++) {
                    int m = wm * 32 + mi * 16 + (lane & 15);
                    ldsm4(a[mi][0], a[mi][1], a[mi][2], a[mi][3],
                          smem_u32(&Ac[m * APITCH + k0 + (lane >> 4) * 8]));
                }
                uint32_t b[4][4];
#pragma unroll
                for (int nj = 0; nj < 4; nj++) {
                    int kk = k0 + (lane & 15);
                    int n = wn * 64 + nj * 16 + (lane >> 4) * 8;
                    ldsm4t(b[nj][0], b[nj][1], b[nj][2], b[nj][3],
                           smem_u32(&Bc[kk * BPITCH_ + n]));
                }
#pragma unroll
                for (int mi = 0; mi < 2; mi++)
#pragma unroll
                    for (int nj = 0; nj < 4; nj++) {
                        mma16816(acc[mi][2 * nj + 0], a[mi], &b[nj][0]);
                        mma16816(acc[mi][2 * nj + 1], a[mi], &b[nj][2]);
                    }
            }
        }
    }
};

// ---------------- generic GEMM: 128x256 CTA tile, 512 threads ---------------
// OUTMODE: 0 = fp16 only, 1 = fp32 only, 2 = both
template <int OUTMODE, bool HASBIAS, bool GELU, bool RESID>
__global__ __launch_bounds__(512, 1)
void hgemm_kernel(const __half* __restrict__ A, const __half* __restrict__ B,
                  const float* __restrict__ bias, const float* __restrict__ resid,
                  float* __restrict__ Cf, __half* __restrict__ Ch)
{
    extern __shared__ __align__(16) char dsm[];
    __half* Asm = (__half*)dsm;
    __half* Bsm = Asm + NSTAGE * A_ST;

    const int nyb = HIDDEN / 256;  // 16
    const int rowBase = (blockIdx.x / nyb) * 128;
    const int colBase = (blockIdx.x % nyb) * 256;

    const int tid = threadIdx.x;
    const int lane = tid & 31;
    const int warp = tid >> 5;     // 0..15
    const int wm = warp >> 2, wn = warp & 3;   // 4x4 warp grid

    float acc[2][8][4];
#pragma unroll
    for (int i = 0; i < 2; i++)
#pragma unroll
        for (int j = 0; j < 8; j++)
#pragma unroll
            for (int k = 0; k < 4; k++) acc[i][j][k] = 0.0f;

    GemmCore<512, 256, BPITCH_G>::run(acc, Asm, Bsm,
                                      A + (size_t)rowBase * HIDDEN, B + colBase,
                                      tid, lane, wm, wn);

    // epilogue
#pragma unroll
    for (int mi = 0; mi < 2; mi++) {
        int r0 = rowBase + wm * 32 + mi * 16 + (lane >> 2);
#pragma unroll
        for (int nj = 0; nj < 8; nj++) {
            int col = colBase + wn * 64 + nj * 8 + (lane & 3) * 2;
            float v0 = acc[mi][nj][0], v1 = acc[mi][nj][1];
            float v2 = acc[mi][nj][2], v3 = acc[mi][nj][3];
            if (HASBIAS) {
                float2 bb = *(const float2*)&bias[col];
                v0 += bb.x; v1 += bb.y; v2 += bb.x; v3 += bb.y;
            }
            if (GELU) {
                v0 = gelu_exact(v0); v1 = gelu_exact(v1);
                v2 = gelu_exact(v2); v3 = gelu_exact(v3);
            }
            if (RESID) {
                float2 ra = *(const float2*)&resid[(size_t)r0 * HIDDEN + col];
                float2 rb = *(const float2*)&resid[(size_t)(r0 + 8) * HIDDEN + col];
                v0 += ra.x; v1 += ra.y; v2 += rb.x; v3 += rb.y;
            }
            if (OUTMODE >= 1) {
                *(float2*)&Cf[(size_t)r0 * HIDDEN + col] = make_float2(v0, v1);
                *(float2*)&Cf[(size_t)(r0 + 8) * HIDDEN + col] = make_float2(v2, v3);
            }
            if (OUTMODE == 0 || OUTMODE == 2) {
                *(__half2*)&Ch[(size_t)r0 * HIDDEN + col] = __floats2half2_rn(v0, v1);
                *(__half2*)&Ch[(size_t)(r0 + 8) * HIDDEN + col] = __floats2half2_rn(v2, v3);
            }
        }
    }
}

// ---------------- fused: xq = (q @ wq)*scale -> latent attention ------------
// Exact measured-good R8 configuration: 128x128 tile, 256 threads, 2 CTA/SM.
#define XQ_PITCH 132
#define ATTN_BODY_BYTES ((128 * XQ_PITCH + 64 * XQ_PITCH + 8 * 64) * 4)
#define ATTN_SMEM_BYTES (ATTN_BODY_BYTES > ATTN_GEMM_SMEM ? ATTN_BODY_BYTES : ATTN_GEMM_SMEM)

__global__ __launch_bounds__(256, 2)
void fused_attn_kernel(const __half* __restrict__ A,   // query fp16 [SEQ,HIDDEN]
                       const __half* __restrict__ B,   // wq fp16 [HIDDEN,HIDDEN]
                       const float* __restrict__ kv,   // kv_latent fp32 [RLAT,HIDDEN]
                       __half* __restrict__ C)         // attn out fp16
{
    extern __shared__ __align__(16) char smem_raw[];
    __half* Asm = (__half*)smem_raw;
    __half* Bsm = Asm + NSTAGE * A_ST;

    const int xb = blockIdx.x / NHEADS;
    const int h  = blockIdx.x % NHEADS;
    const int rowBase = xb * 128;
    const int colBase = h * 128;   // DH = 128

    const int tid = threadIdx.x;
    const int lane = tid & 31;
    const int warp = tid >> 5;     // 0..7
    const int wm = warp >> 1, wn = warp & 1;

    float acc[2][8][4];
#pragma unroll
    for (int i = 0; i < 2; i++)
#pragma unroll
        for (int j = 0; j < 8; j++)
#pragma unroll
            for (int k = 0; k < 4; k++) acc[i][j][k] = 0.0f;

    GemmCore<256, 128, BPITCH_A>::run(acc, Asm, Bsm,
                                      A + (size_t)rowBase * HIDDEN, B + colBase,
                                      tid, lane, wm, wn);

    __syncthreads();   // done with GEMM smem; repurpose for attention

    float* xq  = (float*)smem_raw;              // [128][XQ_PITCH]
    float* kvs = xq + 128 * XQ_PITCH;           // [64][XQ_PITCH]
    float* ps  = kvs + 64 * XQ_PITCH;           // [8][64]

    const float scale = 0.125f;  // R^-0.5
#pragma unroll
    for (int mi = 0; mi < 2; mi++) {
        int r0 = wm * 32 + mi * 16 + (lane >> 2);
#pragma unroll
        for (int nj = 0; nj < 8; nj++) {
            int c = wn * 64 + nj * 8 + (lane & 3) * 2;
            xq[r0 * XQ_PITCH + c]           = acc[mi][nj][0] * scale;
            xq[r0 * XQ_PITCH + c + 1]       = acc[mi][nj][1] * scale;
            xq[(r0 + 8) * XQ_PITCH + c]     = acc[mi][nj][2] * scale;
            xq[(r0 + 8) * XQ_PITCH + c + 1] = acc[mi][nj][3] * scale;
        }
    }
    for (int idx = tid; idx < RLAT * 32; idx += 256) {
        int r = idx >> 5, d4 = idx & 31;
        float4 v = *(const float4*)(kv + (size_t)r * HIDDEN + colBase + (d4 << 2));
        *(float4*)&kvs[r * XQ_PITCH + (d4 << 2)] = v;
    }
    __syncthreads();

    float* pw = ps + warp * 64;
    for (int rr = 0; rr < 16; rr++) {
        int row = (warp << 4) + rr;
        const float* xrow = xq + row * XQ_PITCH;
        const float* k0 = kvs + lane * XQ_PITCH;
        const float* k1 = kvs + (lane + 32) * XQ_PITCH;
        float s0 = 0.0f, s1 = 0.0f;
#pragma unroll 8
        for (int d4 = 0; d4 < 32; d4++) {
            float4 xv = *(const float4*)&xrow[d4 << 2];
            float4 av = *(const float4*)&k0[d4 << 2];
            float4 bv = *(const float4*)&k1[d4 << 2];
            s0 += xv.x * av.x + xv.y * av.y + xv.z * av.z + xv.w * av.w;
            s1 += xv.x * bv.x + xv.y * bv.y + xv.z * bv.z + xv.w * bv.w;
        }
        float m = fmaxf(s0, s1);
#pragma unroll
        for (int off = 16; off > 0; off >>= 1)
            m = fmaxf(m, __shfl_xor_sync(0xffffffffu, m, off));
        float e0 = __expf(s0 - m), e1 = __expf(s1 - m);
        float sum = e0 + e1;
#pragma unroll
        for (int off = 16; off > 0; off >>= 1)
            sum += __shfl_xor_sync(0xffffffffu, sum, off);
        float inv = 1.0f / sum;
        __syncwarp();
        pw[lane] = e0 * inv;
        pw[lane + 32] = e1 * inv;
        __syncwarp();

        float4 o = make_float4(0.f, 0.f, 0.f, 0.f);
#pragma unroll 16
        for (int r = 0; r < 64; r++) {
            float p = pw[r];
            float4 kvv = *(const float4*)&kvs[r * XQ_PITCH + (lane << 2)];
            o.x = fmaf(p, kvv.x, o.x);
            o.y = fmaf(p, kvv.y, o.y);
            o.z = fmaf(p, kvv.z, o.z);
            o.w = fmaf(p, kvv.w, o.w);
        }
        __half* cp = C + (size_t)(rowBase + row) * HIDDEN + colBase + (lane << 2);
        ((__half2*)cp)[0] = __floats2half2_rn(o.x, o.y);
        ((__half2*)cp)[1] = __floats2half2_rn(o.z, o.w);
    }
}

// ---------------- host launcher --------------------------------------------
extern "C" void kernel_launch(void* const* d_in, const int* in_sizes, int n_in,
                              void* d_out, int out_size)
{
    const float* query = (const float*)d_in[0];
    const float* kvlat = (const float*)d_in[1];
    const float* wq    = (const float*)d_in[2];
    const float* wo    = (const float*)d_in[3];
    const float* w1    = (const float*)d_in[4];
    const float* b1    = (const float*)d_in[5];
    const float* w2    = (const float*)d_in[6];
    const float* b2    = (const float*)d_in[7];
    float* y = (float*)d_out;

    __half *qh, *ah, *oh, *hh, *wqh, *woh, *w1h, *w2h;
    float* of;
    cudaGetSymbolAddress((void**)&qh, g_qh);
    cudaGetSymbolAddress((void**)&ah, g_ah);
    cudaGetSymbolAddress((void**)&oh, g_oh);
    cudaGetSymbolAddress((void**)&hh, g_hh);
    cudaGetSymbolAddress((void**)&of, g_of);
    cudaGetSymbolAddress((void**)&wqh, g_wqh);
    cudaGetSymbolAddress((void**)&woh, g_woh);
    cudaGetSymbolAddress((void**)&w1h, g_w1h);
    cudaGetSymbolAddress((void**)&w2h, g_w2h);

    cudaFuncSetAttribute(fused_attn_kernel,
                         cudaFuncAttributeMaxDynamicSharedMemorySize,
                         ATTN_SMEM_BYTES);
    cudaFuncSetAttribute(hgemm_kernel<2, false, false, false>,
                         cudaFuncAttributeMaxDynamicSharedMemorySize,
                         GEMM_SMEM_BYTES);
    cudaFuncSetAttribute(hgemm_kernel<0, true, true, false>,
                         cudaFuncAttributeMaxDynamicSharedMemorySize,
                         GEMM_SMEM_BYTES);
    cudaFuncSetAttribute(hgemm_kernel<1, true, false, true>,
                         cudaFuncAttributeMaxDynamicSharedMemorySize,
                         GEMM_SMEM_BYTES);

    const int wn4 = (HIDDEN * HIDDEN) / 4;
    const int qn4 = (SEQ * HIDDEN) / 4;
    cvt_kernel<<<4096, 256>>>(query, qh, qn4);
    cvt_kernel<<<4096, 256>>>(wq, wqh, wn4);
    cvt_kernel<<<4096, 256>>>(wo, woh, wn4);
    cvt_kernel<<<4096, 256>>>(w1, w1h, wn4);
    cvt_kernel<<<4096, 256>>>(w2, w2h, wn4);

    const int grid_attn = (SEQ / 128) * NHEADS;          // 4096
    const int grid_gemm = (SEQ / 128) * (HIDDEN / 256);  // 2048

    // K1: ah = attention(q @ wq)
    fused_attn_kernel<<<grid_attn, 256, ATTN_SMEM_BYTES>>>(qh, wqh, kvlat, ah);
    // K2: out = ah @ wo  -> fp32 (residual) + fp16 (next GEMM input)
    hgemm_kernel<2, false, false, false><<<grid_gemm, 512, GEMM_SMEM_BYTES>>>(
        ah, woh, nullptr, nullptr, of, oh);
    // K3: hh = gelu(out @ w1 + b1) -> fp16
    hgemm_kernel<0, true, true, false><<<grid_gemm, 512, GEMM_SMEM_BYTES>>>(
        oh, w1h, b1, nullptr, nullptr, hh);
    // K4: y = hh @ w2 + b2 + out  -> fp32
    hgemm_kernel<1, true, false, true><<<grid_gemm, 512, GEMM_SMEM_BYTES>>>(
        hh, w2h, b2, of, y, nullptr);
}

// round 16
// speedup vs baseline: 1.8462x; 1.0717x over previous
#include <cuda_runtime.h>
#include <cuda_fp16.h>
#include <math.h>
#include <stdint.h>

#define SEQ    16384
#define HIDDEN 4096
#define NHEADS 32
#define RLAT   64

#define BM 128
#define BN 128
#define BK 32
#define NSTAGE 6
#define APITCH 40     // fp16 elems per A smem row (80B: conflict-free ldmatrix)
#define BPITCH 136    // fp16 elems per B smem row
#define KTILES (HIDDEN / BK)   // 128

#define A_ST (BM * APITCH)     // halves per A stage
#define B_ST (BK * BPITCH)     // halves per B stage
#define GEMM_SMEM_BYTES ((NSTAGE * (A_ST + B_ST)) * 2)   // 113,664 B

// ---------------- scratch (static device globals; no allocation) -----------
__device__ __half g_qh[(size_t)SEQ * HIDDEN];   // query fp16
__device__ __half g_ah[(size_t)SEQ * HIDDEN];   // attention out fp16
__device__ __half g_oh[(size_t)SEQ * HIDDEN];   // 'out' fp16
__device__ __half g_hh[(size_t)SEQ * HIDDEN];   // gelu hidden fp16
__device__ float  g_of[(size_t)SEQ * HIDDEN];   // 'out' fp32 (residual)
__device__ __half g_wqh[(size_t)HIDDEN * HIDDEN];
__device__ __half g_woh[(size_t)HIDDEN * HIDDEN];
__device__ __half g_w1h[(size_t)HIDDEN * HIDDEN];
__device__ __half g_w2h[(size_t)HIDDEN * HIDDEN];

// ---------------- small helpers -------------------------------------------
__device__ __forceinline__ uint32_t smem_u32(const void* p) {
    return (uint32_t)__cvta_generic_to_shared(p);
}
__device__ __forceinline__ void cp16(uint32_t s, const void* g) {
    asm volatile("cp.async.cg.shared.global [%0], [%1], 16;\n" :: "r"(s), "l"(g));
}
#define CP_COMMIT() asm volatile("cp.async.commit_group;\n")
#define CP_WAIT1()  asm volatile("cp.async.wait_group 1;\n")

__device__ __forceinline__ void ldsm4(uint32_t& r0, uint32_t& r1, uint32_t& r2,
                                      uint32_t& r3, uint32_t a) {
    asm volatile("ldmatrix.sync.aligned.m8n8.x4.shared.b16 {%0,%1,%2,%3}, [%4];\n"
                 : "=r"(r0), "=r"(r1), "=r"(r2), "=r"(r3) : "r"(a));
}
__device__ __forceinline__ void ldsm4t(uint32_t& r0, uint32_t& r1, uint32_t& r2,
                                       uint32_t& r3, uint32_t a) {
    asm volatile("ldmatrix.sync.aligned.m8n8.x4.trans.shared.b16 {%0,%1,%2,%3}, [%4];\n"
                 : "=r"(r0), "=r"(r1), "=r"(r2), "=r"(r3) : "r"(a));
}
__device__ __forceinline__ void mma16816(float* d, const uint32_t* a, const uint32_t* b) {
    asm volatile(
        "mma.sync.aligned.m16n8k16.row.col.f32.f16.f16.f32 "
        "{%0,%1,%2,%3}, {%4,%5,%6,%7}, {%8,%9}, {%0,%1,%2,%3};\n"
        : "+f"(d[0]), "+f"(d[1]), "+f"(d[2]), "+f"(d[3])
        : "r"(a[0]), "r"(a[1]), "r"(a[2]), "r"(a[3]), "r"(b[0]), "r"(b[1]));
}
__device__ __forceinline__ float gelu_exact(float x) {
    return 0.5f * x * (1.0f + erff(x * 0.70710678118654752f));
}

// ---------------- fp32 -> fp16 conversion ----------------------------------
__global__ __launch_bounds__(256)
void cvt_kernel(const float* __restrict__ in, __half* __restrict__ out, int n4) {
    int i = blockIdx.x * blockDim.x + threadIdx.x;
    int stride = gridDim.x * blockDim.x;
    for (; i < n4; i += stride) {
        float4 v = ((const float4*)in)[i];
        ((__half2*)out)[2 * i + 0] = __floats2half2_rn(v.x, v.y);
        ((__half2*)out)[2 * i + 1] = __floats2half2_rn(v.z, v.w);
    }
}

// ---------------- shared mainloop: 6-stage pipeline, 2 tiles per step -------
// Measured-good R8 core (128x128 tile, 32x64 warp tile, acc[2][8][4]);
// only the pipeline cadence changed: one wait+sync+commit per 2 K-tiles.
struct GemmCore {
    __device__ __forceinline__ static void load_tile(
        __half* Asm, __half* Bsm, int u,
        const __half* Ap, const __half* Bp, int arow, int achk, int brow, int bchk)
    {
        __half* A0 = Asm + (u % NSTAGE) * A_ST;
        __half* B0 = Bsm + (u % NSTAGE) * B_ST;
        const int kt = u * BK;
#pragma unroll
        for (int p = 0; p < 2; p++) {
            int r = arow + (p << 6);
            cp16(smem_u32(&A0[r * APITCH + achk * 8]),
                 Ap + (size_t)r * HIDDEN + kt + achk * 8);
        }
#pragma unroll
        for (int p = 0; p < 2; p++) {
            int kk = brow + (p << 4);
            cp16(smem_u32(&B0[kk * BPITCH + bchk * 8]),
                 Bp + (size_t)(kt + kk) * HIDDEN + bchk * 8);
        }
    }

    __device__ __forceinline__ static void run(
        float acc[2][8][4], __half* Asm, __half* Bsm,
        const __half* Ap, const __half* Bp,
        int tid, int lane, int wm, int wn)
    {
        const int arow = tid >> 2, achk = tid & 3;    // A: 128 rows x 4 chunks
        const int brow = tid >> 4, bchk = tid & 15;   // B: 32 rows x 16 chunks

        // prologue: 2 groups of 2 tiles (tiles 0..3)
        load_tile(Asm, Bsm, 0, Ap, Bp, arow, achk, brow, bchk);
        load_tile(Asm, Bsm, 1, Ap, Bp, arow, achk, brow, bchk);
        CP_COMMIT();
        load_tile(Asm, Bsm, 2, Ap, Bp, arow, achk, brow, bchk);
        load_tile(Asm, Bsm, 3, Ap, Bp, arow, achk, brow, bchk);
        CP_COMMIT();

        for (int t = 0; t < KTILES; t += 2) {
            // group holding tiles {t,t+1} has exactly 1 group after it
            CP_WAIT1();
            __syncthreads();

            // prefetch tiles {t+4,t+5} into stages freed by {t-2,t-1}
            int un = t + 4;
            if (un < KTILES) {
                load_tile(Asm, Bsm, un, Ap, Bp, arow, achk, brow, bchk);
                load_tile(Asm, Bsm, un + 1, Ap, Bp, arow, achk, brow, bchk);
            }
            CP_COMMIT();   // empty group in tail keeps wait depth uniform

#pragma unroll
            for (int d = 0; d < 2; d++) {
                int tt = t + d;
                __half* Ac = Asm + (tt % NSTAGE) * A_ST;
                __half* Bc = Bsm + (tt % NSTAGE) * B_ST;
#pragma unroll
                for (int ks = 0; ks < 2; ks++) {
                    const int k0 = ks * 16;
                    uint32_t a[2][4];
#pragma unroll
                    for (int mi = 0; mi < 2; mi++) {
                        int m = wm * 32 + mi * 16 + (lane & 15);
                        ldsm4(a[mi][0], a[mi][1], a[mi][2], a[mi][3],
                              smem_u32(&Ac[m * APITCH + k0 + (lane >> 4) * 8]));
                    }
                    uint32_t b[4][4];
#pragma unroll
                    for (int nj = 0; nj < 4; nj++) {
                        int kk = k0 + (lane & 15);
                        int n = wn * 64 + nj * 16 + (lane >> 4) * 8;
                        ldsm4t(b[nj][0], b[nj][1], b[nj][2], b[nj][3],
                               smem_u32(&Bc[kk * BPITCH + n]));
                    }
#pragma unroll
                    for (int mi = 0; mi < 2; mi++)
#pragma unroll
                        for (int nj = 0; nj < 4; nj++) {
                            mma16816(acc[mi][2 * nj + 0], a[mi], &b[nj][0]);
                            mma16816(acc[mi][2 * nj + 1], a[mi], &b[nj][2]);
                        }
                }
            }
        }
    }
};

// ---------------- generic GEMM: C = epi(A @ B) -----------------------------
// OUTMODE: 0 = fp16 only, 1 = fp32 only, 2 = both
template <int OUTMODE, bool HASBIAS, bool GELU, bool RESID>
__global__ __launch_bounds__(256, 2)
void hgemm_kernel(const __half* __restrict__ A, const __half* __restrict__ B,
                  const float* __restrict__ bias, const float* __restrict__ resid,
                  float* __restrict__ Cf, __half* __restrict__ Ch)
{
    extern __shared__ __align__(16) char dsm[];
    __half* Asm = (__half*)dsm;
    __half* Bsm = Asm + NSTAGE * A_ST;

    const int nyb = HIDDEN / BN;  // 32
    const int xb = blockIdx.x / nyb;
    const int yb = blockIdx.x % nyb;
    const int rowBase = xb * BM;
    const int colBase = yb * BN;

    const int tid = threadIdx.x;
    const int lane = tid & 31;
    const int warp = tid >> 5;
    const int wm = warp >> 1, wn = warp & 1;

    float acc[2][8][4];
#pragma unroll
    for (int i = 0; i < 2; i++)
#pragma unroll
        for (int j = 0; j < 8; j++)
#pragma unroll
            for (int k = 0; k < 4; k++) acc[i][j][k] = 0.0f;

    GemmCore::run(acc, Asm, Bsm,
                  A + (size_t)rowBase * HIDDEN, B + colBase,
                  tid, lane, wm, wn);

    // epilogue
#pragma unroll
    for (int mi = 0; mi < 2; mi++) {
        int r0 = rowBase + wm * 32 + mi * 16 + (lane >> 2);
#pragma unroll
        for (int nj = 0; nj < 8; nj++) {
            int col = colBase + wn * 64 + nj * 8 + (lane & 3) * 2;
            float v0 = acc[mi][nj][0], v1 = acc[mi][nj][1];
            float v2 = acc[mi][nj][2], v3 = acc[mi][nj][3];
            if (HASBIAS) {
                float2 bb = *(const float2*)&bias[col];
                v0 += bb.x; v1 += bb.y; v2 += bb.x; v3 += bb.y;
            }
            if (GELU) {
                v0 = gelu_exact(v0); v1 = gelu_exact(v1);
                v2 = gelu_exact(v2); v3 = gelu_exact(v3);
            }
            if (RESID) {
                float2 ra = *(const float2*)&resid[(size_t)r0 * HIDDEN + col];
                float2 rb = *(const float2*)&resid[(size_t)(r0 + 8) * HIDDEN + col];
                v0 += ra.x; v1 += ra.y; v2 += rb.x; v3 += rb.y;
            }
            if (OUTMODE >= 1) {
                *(float2*)&Cf[(size_t)r0 * HIDDEN + col] = make_float2(v0, v1);
                *(float2*)&Cf[(size_t)(r0 + 8) * HIDDEN + col] = make_float2(v2, v3);
            }
            if (OUTMODE == 0 || OUTMODE == 2) {
                *(__half2*)&Ch[(size_t)r0 * HIDDEN + col] = __floats2half2_rn(v0, v1);
                *(__half2*)&Ch[(size_t)(r0 + 8) * HIDDEN + col] = __floats2half2_rn(v2, v3);
            }
        }
    }
}

// ---------------- fused: xq = (q @ wq)*scale -> latent attention -----------
#define XQ_PITCH 132
#define ATTN_BODY_BYTES ((128 * XQ_PITCH + 64 * XQ_PITCH + 8 * 64) * 4)
#define ATTN_SMEM_BYTES (ATTN_BODY_BYTES > GEMM_SMEM_BYTES ? ATTN_BODY_BYTES : GEMM_SMEM_BYTES)

__global__ __launch_bounds__(256, 2)
void fused_attn_kernel(const __half* __restrict__ A,   // query fp16 [SEQ,HIDDEN]
                       const __half* __restrict__ B,   // wq fp16 [HIDDEN,HIDDEN]
                       const float* __restrict__ kv,   // kv_latent fp32 [RLAT,HIDDEN]
                       __half* __restrict__ C)         // attn out fp16
{
    extern __shared__ __align__(16) char smem_raw[];
    __half* Asm = (__half*)smem_raw;
    __half* Bsm = Asm + NSTAGE * A_ST;

    const int xb = blockIdx.x / NHEADS;
    const int h  = blockIdx.x % NHEADS;
    const int rowBase = xb * BM;
    const int colBase = h * 128;   // DH = 128 = BN

    const int tid = threadIdx.x;
    const int lane = tid & 31;
    const int warp = tid >> 5;
    const int wm = warp >> 1, wn = warp & 1;

    float acc[2][8][4];
#pragma unroll
    for (int i = 0; i < 2; i++)
#pragma unroll
        for (int j = 0; j < 8; j++)
#pragma unroll
            for (int k = 0; k < 4; k++) acc[i][j][k] = 0.0f;

    GemmCore::run(acc, Asm, Bsm,
                  A + (size_t)rowBase * HIDDEN, B + colBase,
                  tid, lane, wm, wn);

    __syncthreads();   // done with GEMM smem; repurpose for attention

    float* xq  = (float*)smem_raw;              // [128][XQ_PITCH]
    float* kvs = xq + 128 * XQ_PITCH;           // [64][XQ_PITCH]
    float* ps  = kvs + 64 * XQ_PITCH;           // [8][64]

    const float scale = 0.125f;  // R^-0.5
#pragma unroll
    for (int mi = 0; mi < 2; mi++) {
        int r0 = wm * 32 + mi * 16 + (lane >> 2);
#pragma unroll
        for (int nj = 0; nj < 8; nj++) {
            int c = wn * 64 + nj * 8 + (lane & 3) * 2;
            xq[r0 * XQ_PITCH + c]           = acc[mi][nj][0] * scale;
            xq[r0 * XQ_PITCH + c + 1]       = acc[mi][nj][1] * scale;
            xq[(r0 + 8) * XQ_PITCH + c]     = acc[mi][nj][2] * scale;
            xq[(r0 + 8) * XQ_PITCH + c + 1] = acc[mi][nj][3] * scale;
        }
    }
    for (int idx = tid; idx < RLAT * 32; idx += 256) {
        int r = idx >> 5, d4 = idx & 31;
        float4 v = *(const float4*)(kv + (size_t)r * HIDDEN + colBase + (d4 << 2));
        *(float4*)&kvs[r * XQ_PITCH + (d4 << 2)] = v;
    }
    __syncthreads();

    float* pw = ps + warp * 64;
    for (int rr = 0; rr < 16; rr++) {
        int row = (warp << 4) + rr;
        const float* xrow = xq + row * XQ_PITCH;
        const float* k0 = kvs + lane * XQ_PITCH;
        const float* k1 = kvs + (lane + 32) * XQ_PITCH;
        float s0 = 0.0f, s1 = 0.0f;
#pragma unroll 8
        for (int d4 = 0; d4 < 32; d4++) {
            float4 xv = *(const float4*)&xrow[d4 << 2];
            float4 av = *(const float4*)&k0[d4 << 2];
            float4 bv = *(const float4*)&k1[d4 << 2];
            s0 += xv.x * av.x + xv.y * av.y + xv.z * av.z + xv.w * av.w;
            s1 += xv.x * bv.x + xv.y * bv.y + xv.z * bv.z + xv.w * bv.w;
        }
        float m = fmaxf(s0, s1);
#pragma unroll
        for (int off = 16; off > 0; off >>= 1)
            m = fmaxf(m, __shfl_xor_sync(0xffffffffu, m, off));
        float e0 = __expf(s0 - m), e1 = __expf(s1 - m);
        float sum = e0 + e1;
#pragma unroll
        for (int off = 16; off > 0; off >>= 1)
            sum += __shfl_xor_sync(0xffffffffu, sum, off);
        float inv = 1.0f / sum;
        __syncwarp();
        pw[lane] = e0 * inv;
        pw[lane + 32] = e1 * inv;
        __syncwarp();

        float4 o = make_float4(0.f, 0.f, 0.f, 0.f);
#pragma unroll 16
        for (int r = 0; r < 64; r++) {
            float p = pw[r];
            float4 kvv = *(const float4*)&kvs[r * XQ_PITCH + (lane << 2)];
            o.x = fmaf(p, kvv.x, o.x);
            o.y = fmaf(p, kvv.y, o.y);
            o.z = fmaf(p, kvv.z, o.z);
            o.w = fmaf(p, kvv.w, o.w);
        }
        __half* cp = C + (size_t)(rowBase + row) * HIDDEN + colBase + (lane << 2);
        ((__half2*)cp)[0] = __floats2half2_rn(o.x, o.y);
        ((__half2*)cp)[1] = __floats2half2_rn(o.z, o.w);
    }
}

// ---------------- host launcher --------------------------------------------
extern "C" void kernel_launch(void* const* d_in, const int* in_sizes, int n_in,
                              void* d_out, int out_size)
{
    const float* query = (const float*)d_in[0];
    const float* kvlat = (const float*)d_in[1];
    const float* wq    = (const float*)d_in[2];
    const float* wo    = (const float*)d_in[3];
    const float* w1    = (const float*)d_in[4];
    const float* b1    = (const float*)d_in[5];
    const float* w2    = (const float*)d_in[6];
    const float* b2    = (const float*)d_in[7];
    float* y = (float*)d_out;

    __half *qh, *ah, *oh, *hh, *wqh, *woh, *w1h, *w2h;
    float* of;
    cudaGetSymbolAddress((void**)&qh, g_qh);
    cudaGetSymbolAddress((void**)&ah, g_ah);
    cudaGetSymbolAddress((void**)&oh, g_oh);
    cudaGetSymbolAddress((void**)&hh, g_hh);
    cudaGetSymbolAddress((void**)&of, g_of);
    cudaGetSymbolAddress((void**)&wqh, g_wqh);
    cudaGetSymbolAddress((void**)&woh, g_woh);
    cudaGetSymbolAddress((void**)&w1h, g_w1h);
    cudaGetSymbolAddress((void**)&w2h, g_w2h);

    cudaFuncSetAttribute(fused_attn_kernel,
                         cudaFuncAttributeMaxDynamicSharedMemorySize,
                         ATTN_SMEM_BYTES);
    cudaFuncSetAttribute(hgemm_kernel<2, false, false, false>,
                         cudaFuncAttributeMaxDynamicSharedMemorySize,
                         GEMM_SMEM_BYTES);
    cudaFuncSetAttribute(hgemm_kernel<0, true, true, false>,
                         cudaFuncAttributeMaxDynamicSharedMemorySize,
                         GEMM_SMEM_BYTES);
    cudaFuncSetAttribute(hgemm_kernel<1, true, false, true>,
                         cudaFuncAttributeMaxDynamicSharedMemorySize,
                         GEMM_SMEM_BYTES);

    const int wn4 = (HIDDEN * HIDDEN) / 4;
    const int qn4 = (SEQ * HIDDEN) / 4;
    cvt_kernel<<<4096, 256>>>(query, qh, qn4);
    cvt_kernel<<<4096, 256>>>(wq, wqh, wn4);
    cvt_kernel<<<4096, 256>>>(wo, woh, wn4);
    cvt_kernel<<<4096, 256>>>(w1, w1h, wn4);
    cvt_kernel<<<4096, 256>>>(w2, w2h, wn4);

    const int grid = (SEQ / BM) * (HIDDEN / BN);  // 4096
    dim3 blk(256);

    // K1: ah = attention(q @ wq)
    fused_attn_kernel<<<grid, blk, ATTN_SMEM_BYTES>>>(qh, wqh, kvlat, ah);
    // K2: out = ah @ wo  -> fp32 (residual) + fp16 (next GEMM input)
    hgemm_kernel<2, false, false, false><<<grid, blk, GEMM_SMEM_BYTES>>>(
        ah, woh, nullptr, nullptr, of, oh);
    // K3: hh = gelu(out @ w1 + b1) -> fp16
    hgemm_kernel<0, true, true, false><<<grid, blk, GEMM_SMEM_BYTES>>>(
        oh, w1h, b1, nullptr, nullptr, hh);
    // K4: y = hh @ w2 + b2 + out  -> fp32
    hgemm_kernel<1, true, false, true><<<grid, blk, GEMM_SMEM_BYTES>>>(
        hh, w2h, b2, of, y, nullptr);
}

// round 17
// speedup vs baseline: 1.9247x; 1.0425x over previous
#include <cuda_runtime.h>
#include <cuda_fp16.h>
#include <math.h>
#include <stdint.h>

#define SEQ    16384
#define HIDDEN 4096
#define NHEADS 32
#define RLAT   64

#define BM 128
#define BN 128
#define BK 32
#define NSTAGE 4
#define APITCH 40     // fp16 elems per A smem row (80B: conflict-free ldmatrix)
#define BPITCH 136    // fp16 elems per B smem row
#define KTILES (HIDDEN / BK)   // 128

#define A_ST (BM * APITCH)     // halves per A stage
#define B_ST (BK * BPITCH)     // halves per B stage
#define GEMM_SMEM_BYTES ((NSTAGE * (A_ST + B_ST)) * 2)   // 75,776 B

// ---------------- scratch (static device globals; no allocation) -----------
__device__ __half g_qh[(size_t)SEQ * HIDDEN];   // query fp16
__device__ __half g_ah[(size_t)SEQ * HIDDEN];   // attention out fp16
__device__ __half g_oh[(size_t)SEQ * HIDDEN];   // 'out' fp16 (GEMM input + residual)
__device__ __half g_hh[(size_t)SEQ * HIDDEN];   // gelu hidden fp16
__device__ __half g_wqh[(size_t)HIDDEN * HIDDEN];
__device__ __half g_woh[(size_t)HIDDEN * HIDDEN];
__device__ __half g_w1h[(size_t)HIDDEN * HIDDEN];
__device__ __half g_w2h[(size_t)HIDDEN * HIDDEN];

// ---------------- small helpers -------------------------------------------
__device__ __forceinline__ uint32_t smem_u32(const void* p) {
    return (uint32_t)__cvta_generic_to_shared(p);
}
__device__ __forceinline__ void cp16(uint32_t s, const void* g) {
    asm volatile("cp.async.cg.shared.global [%0], [%1], 16;\n" :: "r"(s), "l"(g));
}
#define CP_COMMIT() asm volatile("cp.async.commit_group;\n")
#define CP_WAIT2()  asm volatile("cp.async.wait_group 2;\n")

__device__ __forceinline__ void ldsm4(uint32_t& r0, uint32_t& r1, uint32_t& r2,
                                      uint32_t& r3, uint32_t a) {
    asm volatile("ldmatrix.sync.aligned.m8n8.x4.shared.b16 {%0,%1,%2,%3}, [%4];\n"
                 : "=r"(r0), "=r"(r1), "=r"(r2), "=r"(r3) : "r"(a));
}
__device__ __forceinline__ void ldsm4t(uint32_t& r0, uint32_t& r1, uint32_t& r2,
                                       uint32_t& r3, uint32_t a) {
    asm volatile("ldmatrix.sync.aligned.m8n8.x4.trans.shared.b16 {%0,%1,%2,%3}, [%4];\n"
                 : "=r"(r0), "=r"(r1), "=r"(r2), "=r"(r3) : "r"(a));
}
__device__ __forceinline__ void mma16816(float* d, const uint32_t* a, const uint32_t* b) {
    asm volatile(
        "mma.sync.aligned.m16n8k16.row.col.f32.f16.f16.f32 "
        "{%0,%1,%2,%3}, {%4,%5,%6,%7}, {%8,%9}, {%0,%1,%2,%3};\n"
        : "+f"(d[0]), "+f"(d[1]), "+f"(d[2]), "+f"(d[3])
        : "r"(a[0]), "r"(a[1]), "r"(a[2]), "r"(a[3]), "r"(b[0]), "r"(b[1]));
}
__device__ __forceinline__ float gelu_exact(float x) {
    return 0.5f * x * (1.0f + erff(x * 0.70710678118654752f));
}

// ---------------- fp32 -> fp16 conversion ----------------------------------
__global__ __launch_bounds__(256)
void cvt_kernel(const float* __restrict__ in, __half* __restrict__ out, int n4) {
    int i = blockIdx.x * blockDim.x + threadIdx.x;
    int stride = gridDim.x * blockDim.x;
    for (; i < n4; i += stride) {
        float4 v = ((const float4*)in)[i];
        ((__half2*)out)[2 * i + 0] = __floats2half2_rn(v.x, v.y);
        ((__half2*)out)[2 * i + 1] = __floats2half2_rn(v.z, v.w);
    }
}

// ---------------- shared mainloop: measured-good R8 core --------------------
// 4-stage cp.async pipeline; 128x128 CTA tile; 32x64 warp tile; acc[2][8][4].
struct GemmCore {
    __device__ __forceinline__ static void load_tile(
        __half* Asm, __half* Bsm, int u,
        const __half* Ap, const __half* Bp, int arow, int achk, int brow, int bchk)
    {
        __half* A0 = Asm + (u & (NSTAGE - 1)) * A_ST;
        __half* B0 = Bsm + (u & (NSTAGE - 1)) * B_ST;
        const int kt = u * BK;
#pragma unroll
        for (int p = 0; p < 2; p++) {
            int r = arow + (p << 6);
            cp16(smem_u32(&A0[r * APITCH + achk * 8]),
                 Ap + (size_t)r * HIDDEN + kt + achk * 8);
        }
#pragma unroll
        for (int p = 0; p < 2; p++) {
            int kk = brow + (p << 4);
            cp16(smem_u32(&B0[kk * BPITCH + bchk * 8]),
                 Bp + (size_t)(kt + kk) * HIDDEN + bchk * 8);
        }
    }

    __device__ __forceinline__ static void run(
        float acc[2][8][4], __half* Asm, __half* Bsm,
        const __half* Ap, const __half* Bp,
        int tid, int lane, int wm, int wn)
    {
        const int arow = tid >> 2, achk = tid & 3;    // A: 128 rows x 4 chunks
        const int brow = tid >> 4, bchk = tid & 15;   // B: 32 rows x 16 chunks

        // prologue: tiles 0..NSTAGE-2 (one commit group each)
#pragma unroll
        for (int u = 0; u < NSTAGE - 1; u++) {
            load_tile(Asm, Bsm, u, Ap, Bp, arow, achk, brow, bchk);
            CP_COMMIT();
        }

        for (int t = 0; t < KTILES; t++) {
            // group for tile t has exactly (NSTAGE-2)=2 groups after it
            CP_WAIT2();
            __syncthreads();

            int un = t + NSTAGE - 1;
            if (un < KTILES)
                load_tile(Asm, Bsm, un, Ap, Bp, arow, achk, brow, bchk);
            CP_COMMIT();   // empty group in tail keeps wait depth uniform

            __half* Ac = Asm + (t & (NSTAGE - 1)) * A_ST;
            __half* Bc = Bsm + (t & (NSTAGE - 1)) * B_ST;
#pragma unroll
            for (int ks = 0; ks < 2; ks++) {
                const int k0 = ks * 16;
                uint32_t a[2][4];
#pragma unroll
                for (int mi = 0; mi < 2; mi++) {
                    int m = wm * 32 + mi * 16 + (lane & 15);
                    ldsm4(a[mi][0], a[mi][1], a[mi][2], a[mi][3],
                          smem_u32(&Ac[m * APITCH + k0 + (lane >> 4) * 8]));
                }
                uint32_t b[4][4];
#pragma unroll
                for (int nj = 0; nj < 4; nj++) {
                    int kk = k0 + (lane & 15);
                    int n = wn * 64 + nj * 16 + (lane >> 4) * 8;
                    ldsm4t(b[nj][0], b[nj][1], b[nj][2], b[nj][3],
                           smem_u32(&Bc[kk * BPITCH + n]));
                }
#pragma unroll
                for (int mi = 0; mi < 2; mi++)
#pragma unroll
                    for (int nj = 0; nj < 4; nj++) {
                        mma16816(acc[mi][2 * nj + 0], a[mi], &b[nj][0]);
                        mma16816(acc[mi][2 * nj + 1], a[mi], &b[nj][2]);
                    }
            }
        }
    }
};

// ---------------- generic GEMM: C = epi(A @ B) -----------------------------
// OUTMODE: 0 = fp16 only, 1 = fp32 only. RESID reads fp16.
template <int OUTMODE, bool HASBIAS, bool GELU, bool RESID>
__global__ __launch_bounds__(256, 2)
void hgemm_kernel(const __half* __restrict__ A, const __half* __restrict__ B,
                  const float* __restrict__ bias, const __half* __restrict__ resid,
                  float* __restrict__ Cf, __half* __restrict__ Ch)
{
    extern __shared__ __align__(16) char dsm[];
    __half* Asm = (__half*)dsm;
    __half* Bsm = Asm + NSTAGE * A_ST;

    const int nyb = HIDDEN / BN;  // 32
    const int xb = blockIdx.x / nyb;
    const int yb = blockIdx.x % nyb;
    const int rowBase = xb * BM;
    const int colBase = yb * BN;

    const int tid = threadIdx.x;
    const int lane = tid & 31;
    const int warp = tid >> 5;
    const int wm = warp >> 1, wn = warp & 1;

    float acc[2][8][4];
#pragma unroll
    for (int i = 0; i < 2; i++)
#pragma unroll
        for (int j = 0; j < 8; j++)
#pragma unroll
            for (int k = 0; k < 4; k++) acc[i][j][k] = 0.0f;

    GemmCore::run(acc, Asm, Bsm,
                  A + (size_t)rowBase * HIDDEN, B + colBase,
                  tid, lane, wm, wn);

    // epilogue
#pragma unroll
    for (int mi = 0; mi < 2; mi++) {
        int r0 = rowBase + wm * 32 + mi * 16 + (lane >> 2);
#pragma unroll
        for (int nj = 0; nj < 8; nj++) {
            int col = colBase + wn * 64 + nj * 8 + (lane & 3) * 2;
            float v0 = acc[mi][nj][0], v1 = acc[mi][nj][1];
            float v2 = acc[mi][nj][2], v3 = acc[mi][nj][3];
            if (HASBIAS) {
                float2 bb = *(const float2*)&bias[col];
                v0 += bb.x; v1 += bb.y; v2 += bb.x; v3 += bb.y;
            }
            if (GELU) {
                v0 = gelu_exact(v0); v1 = gelu_exact(v1);
                v2 = gelu_exact(v2); v3 = gelu_exact(v3);
            }
            if (RESID) {
                __half2 ra = *(const __half2*)&resid[(size_t)r0 * HIDDEN + col];
                __half2 rb = *(const __half2*)&resid[(size_t)(r0 + 8) * HIDDEN + col];
                float2 raf = __half22float2(ra);
                float2 rbf = __half22float2(rb);
                v0 += raf.x; v1 += raf.y; v2 += rbf.x; v3 += rbf.y;
            }
            if (OUTMODE == 1) {
                *(float2*)&Cf[(size_t)r0 * HIDDEN + col] = make_float2(v0, v1);
                *(float2*)&Cf[(size_t)(r0 + 8) * HIDDEN + col] = make_float2(v2, v3);
            } else {
                *(__half2*)&Ch[(size_t)r0 * HIDDEN + col] = __floats2half2_rn(v0, v1);
                *(__half2*)&Ch[(size_t)(r0 + 8) * HIDDEN + col] = __floats2half2_rn(v2, v3);
            }
        }
    }
}

// ---------------- fused: xq = (q @ wq)*scale -> latent attention -----------
#define XQ_PITCH 132
#define ATTN_BODY_BYTES ((128 * XQ_PITCH + 64 * XQ_PITCH + 8 * 64) * 4)
#define ATTN_SMEM_BYTES (ATTN_BODY_BYTES > GEMM_SMEM_BYTES ? ATTN_BODY_BYTES : GEMM_SMEM_BYTES)

__global__ __launch_bounds__(256, 2)
void fused_attn_kernel(const __half* __restrict__ A,   // query fp16 [SEQ,HIDDEN]
                       const __half* __restrict__ B,   // wq fp16 [HIDDEN,HIDDEN]
                       const float* __restrict__ kv,   // kv_latent fp32 [RLAT,HIDDEN]
                       __half* __restrict__ C)         // attn out fp16
{
    extern __shared__ __align__(16) char smem_raw[];
    __half* Asm = (__half*)smem_raw;
    __half* Bsm = Asm + NSTAGE * A_ST;

    const int xb = blockIdx.x / NHEADS;
    const int h  = blockIdx.x % NHEADS;
    const int rowBase = xb * BM;
    const int colBase = h * 128;   // DH = 128 = BN

    const int tid = threadIdx.x;
    const int lane = tid & 31;
    const int warp = tid >> 5;
    const int wm = warp >> 1, wn = warp & 1;

    float acc[2][8][4];
#pragma unroll
    for (int i = 0; i < 2; i++)
#pragma unroll
        for (int j = 0; j < 8; j++)
#pragma unroll
            for (int k = 0; k < 4; k++) acc[i][j][k] = 0.0f;

    GemmCore::run(acc, Asm, Bsm,
                  A + (size_t)rowBase * HIDDEN, B + colBase,
                  tid, lane, wm, wn);

    __syncthreads();   // done with GEMM smem; repurpose for attention

    float* xq  = (float*)smem_raw;              // [128][XQ_PITCH]
    float* kvs = xq + 128 * XQ_PITCH;           // [64][XQ_PITCH]
    float* ps  = kvs + 64 * XQ_PITCH;           // [8][64]

    const float scale = 0.125f;  // R^-0.5
#pragma unroll
    for (int mi = 0; mi < 2; mi++) {
        int r0 = wm * 32 + mi * 16 + (lane >> 2);
#pragma unroll
        for (int nj = 0; nj < 8; nj++) {
            int c = wn * 64 + nj * 8 + (lane & 3) * 2;
            xq[r0 * XQ_PITCH + c]           = acc[mi][nj][0] * scale;
            xq[r0 * XQ_PITCH + c + 1]       = acc[mi][nj][1] * scale;
            xq[(r0 + 8) * XQ_PITCH + c]     = acc[mi][nj][2] * scale;
            xq[(r0 + 8) * XQ_PITCH + c + 1] = acc[mi][nj][3] * scale;
        }
    }
    for (int idx = tid; idx < RLAT * 32; idx += 256) {
        int r = idx >> 5, d4 = idx & 31;
        float4 v = *(const float4*)(kv + (size_t)r * HIDDEN + colBase + (d4 << 2));
        *(float4*)&kvs[r * XQ_PITCH + (d4 << 2)] = v;
    }
    __syncthreads();

    float* pw = ps + warp * 64;
    for (int rr = 0; rr < 16; rr++) {
        int row = (warp << 4) + rr;
        const float* xrow = xq + row * XQ_PITCH;
        const float* k0 = kvs + lane * XQ_PITCH;
        const float* k1 = kvs + (lane + 32) * XQ_PITCH;
        float s0 = 0.0f, s1 = 0.0f;
#pragma unroll 8
        for (int d4 = 0; d4 < 32; d4++) {
            float4 xv = *(const float4*)&xrow[d4 << 2];
            float4 av = *(const float4*)&k0[d4 << 2];
            float4 bv = *(const float4*)&k1[d4 << 2];
            s0 += xv.x * av.x + xv.y * av.y + xv.z * av.z + xv.w * av.w;
            s1 += xv.x * bv.x + xv.y * bv.y + xv.z * bv.z + xv.w * bv.w;
        }
        float m = fmaxf(s0, s1);
#pragma unroll
        for (int off = 16; off > 0; off >>= 1)
            m = fmaxf(m, __shfl_xor_sync(0xffffffffu, m, off));
        float e0 = __expf(s0 - m), e1 = __expf(s1 - m);
        float sum = e0 + e1;
#pragma unroll
        for (int off = 16; off > 0; off >>= 1)
            sum += __shfl_xor_sync(0xffffffffu, sum, off);
        float inv = 1.0f / sum;
        __syncwarp();
        pw[lane] = e0 * inv;
        pw[lane + 32] = e1 * inv;
        __syncwarp();

        float4 o = make_float4(0.f, 0.f, 0.f, 0.f);
#pragma unroll 16
        for (int r = 0; r < 64; r++) {
            float p = pw[r];
            float4 kvv = *(const float4*)&kvs[r * XQ_PITCH + (lane << 2)];
            o.x = fmaf(p, kvv.x, o.x);
            o.y = fmaf(p, kvv.y, o.y);
            o.z = fmaf(p, kvv.z, o.z);
            o.w = fmaf(p, kvv.w, o.w);
        }
        __half* cp = C + (size_t)(rowBase + row) * HIDDEN + colBase + (lane << 2);
        ((__half2*)cp)[0] = __floats2half2_rn(o.x, o.y);
        ((__half2*)cp)[1] = __floats2half2_rn(o.z, o.w);
    }
}

// ---------------- host launcher --------------------------------------------
extern "C" void kernel_launch(void* const* d_in, const int* in_sizes, int n_in,
                              void* d_out, int out_size)
{
    const float* query = (const float*)d_in[0];
    const float* kvlat = (const float*)d_in[1];
    const float* wq    = (const float*)d_in[2];
    const float* wo    = (const float*)d_in[3];
    const float* w1    = (const float*)d_in[4];
    const float* b1    = (const float*)d_in[5];
    const float* w2    = (const float*)d_in[6];
    const float* b2    = (const float*)d_in[7];
    float* y = (float*)d_out;

    __half *qh, *ah, *oh, *hh, *wqh, *woh, *w1h, *w2h;
    cudaGetSymbolAddress((void**)&qh, g_qh);
    cudaGetSymbolAddress((void**)&ah, g_ah);
    cudaGetSymbolAddress((void**)&oh, g_oh);
    cudaGetSymbolAddress((void**)&hh, g_hh);
    cudaGetSymbolAddress((void**)&wqh, g_wqh);
    cudaGetSymbolAddress((void**)&woh, g_woh);
    cudaGetSymbolAddress((void**)&w1h, g_w1h);
    cudaGetSymbolAddress((void**)&w2h, g_w2h);

    cudaFuncSetAttribute(fused_attn_kernel,
                         cudaFuncAttributeMaxDynamicSharedMemorySize,
                         ATTN_SMEM_BYTES);
    cudaFuncSetAttribute(hgemm_kernel<0, false, false, false>,
                         cudaFuncAttributeMaxDynamicSharedMemorySize,
                         GEMM_SMEM_BYTES);
    cudaFuncSetAttribute(hgemm_kernel<0, true, true, false>,
                         cudaFuncAttributeMaxDynamicSharedMemorySize,
                         GEMM_SMEM_BYTES);
    cudaFuncSetAttribute(hgemm_kernel<1, true, false, true>,
                         cudaFuncAttributeMaxDynamicSharedMemorySize,
                         GEMM_SMEM_BYTES);

    const int wn4 = (HIDDEN * HIDDEN) / 4;
    const int qn4 = (SEQ * HIDDEN) / 4;
    cvt_kernel<<<4096, 256>>>(query, qh, qn4);
    cvt_kernel<<<4096, 256>>>(wq, wqh, wn4);
    cvt_kernel<<<4096, 256>>>(wo, woh, wn4);
    cvt_kernel<<<4096, 256>>>(w1, w1h, wn4);
    cvt_kernel<<<4096, 256>>>(w2, w2h, wn4);

    const int grid = (SEQ / BM) * (HIDDEN / BN);  // 4096
    dim3 blk(256);

    // K1: ah = attention(q @ wq)
    fused_attn_kernel<<<grid, blk, ATTN_SMEM_BYTES>>>(qh, wqh, kvlat, ah);
    // K2: oh = ah @ wo   (fp16; serves as both K3 input and K4 residual)
    hgemm_kernel<0, false, false, false><<<grid, blk, GEMM_SMEM_BYTES>>>(
        ah, woh, nullptr, nullptr, nullptr, oh);
    // K3: hh = gelu(oh @ w1 + b1) -> fp16
    hgemm_kernel<0, true, true, false><<<grid, blk, GEMM_SMEM_BYTES>>>(
        oh, w1h, b1, nullptr, nullptr, hh);
    // K4: y = hh @ w2 + b2 + oh  -> fp32
    hgemm_kernel<1, true, false, true><<<grid, blk, GEMM_SMEM_BYTES>>>(
        hh, w2h, b2, oh, y, nullptr);
}